// round 13
// baseline (speedup 1.0000x reference)
#include <cuda_runtime.h>
#include <cstdint>

// Problem constants (fixed by the reference)
#define NMAX 100000
#define EMAX 1600000
#define FDIM 128

// ---------------- scratch (static device globals; no runtime allocation) ----
__device__ float g_T[(size_t)NMAX * FDIM];   // GEMM output per layer
__device__ float g_H[(size_t)NMAX * FDIM];   // layer activations
__device__ int   g_rowptr[NMAX + 1];
__device__ int   g_cursor[NMAX];
__device__ int   g_colS[EMAX];
__device__ float g_wS[EMAX];
__device__ int   g_bsum[256];

// ---------------- CSR build --------------------------------------------------
__global__ void k_zero_cursor(int n) {
    int i = blockIdx.x * blockDim.x + threadIdx.x;
    if (i < n) g_cursor[i] = 0;
}

__global__ void k_hist(const int* __restrict__ erow, int E) {
    int e = blockIdx.x * blockDim.x + threadIdx.x;
    if (e < E) atomicAdd(&g_cursor[erow[e]], 1);
}

// per-block exclusive scan of degrees (chunk = 1024), block totals to g_bsum
__global__ void k_scan1(int n) {
    __shared__ int s[1024];
    int i = blockIdx.x * 1024 + threadIdx.x;
    int v = (i < n) ? g_cursor[i] : 0;
    s[threadIdx.x] = v;
    __syncthreads();
#pragma unroll
    for (int off = 1; off < 1024; off <<= 1) {
        int t = 0;
        if ((int)threadIdx.x >= off) t = s[threadIdx.x - off];
        __syncthreads();
        s[threadIdx.x] += t;
        __syncthreads();
    }
    if (i < n) g_rowptr[i] = s[threadIdx.x] - v;  // exclusive within block
    if (threadIdx.x == 1023) g_bsum[blockIdx.x] = s[1023];
}

// serial exclusive scan of the (<=98) block sums — trivial
__global__ void k_scan2(int nb) {
    if (threadIdx.x == 0 && blockIdx.x == 0) {
        int acc = 0;
        for (int b = 0; b < nb; b++) { int t = g_bsum[b]; g_bsum[b] = acc; acc += t; }
    }
}

__global__ void k_scan3(int n, int E) {
    int i = blockIdx.x * 1024 + threadIdx.x;
    if (i < n) {
        int rp = g_rowptr[i] + g_bsum[blockIdx.x];
        g_rowptr[i] = rp;
        g_cursor[i] = rp;
    }
    if (blockIdx.x == 0 && threadIdx.x == 0) g_rowptr[n] = E;
}

__global__ void k_scatter(const int* __restrict__ erow, const int* __restrict__ ecol,
                          const float* __restrict__ ew, int E) {
    int e = blockIdx.x * blockDim.x + threadIdx.x;
    if (e < E) {
        int r = erow[e];
        int p = atomicAdd(&g_cursor[r], 1);
        g_colS[p] = ecol[e];
        g_wS[p]   = ew[e];
    }
}

// ---------------- GEMM: C[N,128] = A[N,128] @ W[128,128] (fp32) --------------
// BM=64 rows/block, 256 threads, 4x8 micro-tile per thread.
// A tile [64][132] (padded) + full W [128][128] in dynamic SMEM (~97 KB).
#define GEMM_BM 64
#define GEMM_THREADS 256
#define AS_LD 132
#define GEMM_SMEM_BYTES ((GEMM_BM * AS_LD + 128 * 128) * 4)

__global__ __launch_bounds__(GEMM_THREADS) void k_gemm(
    const float* __restrict__ A, const float* __restrict__ W,
    float* __restrict__ C, int N)
{
    extern __shared__ float sm[];
    float* As = sm;                    // [64][132]
    float* Ws = sm + GEMM_BM * AS_LD;  // [128][128]

    const int tid = threadIdx.x;
    const int m_base = blockIdx.x * GEMM_BM;

    // load W: 128x128 = 4096 float4, 16 per thread, coalesced
    {
        const float4* W4 = (const float4*)W;
        float4* Ws4 = (float4*)Ws;
#pragma unroll
        for (int i = 0; i < 16; i++) Ws4[tid + i * GEMM_THREADS] = W4[tid + i * GEMM_THREADS];
    }
    // load A tile: 64x128 = 2048 float4, 8 per thread, coalesced, guarded
    {
        const float4* A4 = (const float4*)A;
#pragma unroll
        for (int i = 0; i < 8; i++) {
            int idx = tid + i * GEMM_THREADS;   // 0..2047
            int r  = idx >> 5;                  // row within tile
            int kq = idx & 31;                  // float4 along K
            float4 v = make_float4(0.f, 0.f, 0.f, 0.f);
            if (m_base + r < N) v = A4[(size_t)(m_base + r) * 32 + kq];
            *(float4*)(As + r * AS_LD + kq * 4) = v;   // AS_LD*4=528B, 16B-aligned
        }
    }
    __syncthreads();

    const int tx = tid & 15;          // n0 = tx*8
    const int ty = tid >> 4;          // m0 = ty*4
    const int m0 = ty * 4;
    const int n0 = tx * 8;

    float acc[4][8];
#pragma unroll
    for (int i = 0; i < 4; i++)
#pragma unroll
        for (int j = 0; j < 8; j++) acc[i][j] = 0.f;

#pragma unroll 8
    for (int k = 0; k < 128; k++) {
        float a[4];
#pragma unroll
        for (int i = 0; i < 4; i++) a[i] = As[(m0 + i) * AS_LD + k];
        float4 b0 = *(const float4*)(Ws + k * 128 + n0);
        float4 b1 = *(const float4*)(Ws + k * 128 + n0 + 4);
#pragma unroll
        for (int i = 0; i < 4; i++) {
            acc[i][0] += a[i] * b0.x;  acc[i][1] += a[i] * b0.y;
            acc[i][2] += a[i] * b0.z;  acc[i][3] += a[i] * b0.w;
            acc[i][4] += a[i] * b1.x;  acc[i][5] += a[i] * b1.y;
            acc[i][6] += a[i] * b1.z;  acc[i][7] += a[i] * b1.w;
        }
    }

    float4* C4 = (float4*)C;
#pragma unroll
    for (int i = 0; i < 4; i++) {
        int row = m_base + m0 + i;
        if (row < N) {
            float4 o0 = make_float4(acc[i][0], acc[i][1], acc[i][2], acc[i][3]);
            float4 o1 = make_float4(acc[i][4], acc[i][5], acc[i][6], acc[i][7]);
            C4[(size_t)row * 32 + (n0 >> 2)]     = o0;
            C4[(size_t)row * 32 + (n0 >> 2) + 1] = o1;
        }
    }
}

// ---------------- SpMM (CSR) + ReLU: O[r] = relu(sum_e w_e * T[col_e]) ------
// warp per row, lane handles one float4 (128 floats / 32 lanes)
__global__ __launch_bounds__(256) void k_spmm_relu(
    const float* __restrict__ T, float* __restrict__ O, int N)
{
    int warp = (blockIdx.x * blockDim.x + threadIdx.x) >> 5;
    int lane = threadIdx.x & 31;
    if (warp >= N) return;

    int s = g_rowptr[warp];
    int e = g_rowptr[warp + 1];

    float ax = 0.f, ay = 0.f, az = 0.f, aw = 0.f;
    const float4* T4 = (const float4*)T;

    int p = s;
#pragma unroll 1
    for (; p + 2 <= e; p += 2) {
        int   c0 = g_colS[p],     c1 = g_colS[p + 1];
        float w0 = g_wS[p],       w1 = g_wS[p + 1];
        float4 v0 = T4[(size_t)c0 * 32 + lane];
        float4 v1 = T4[(size_t)c1 * 32 + lane];
        ax += w0 * v0.x; ay += w0 * v0.y; az += w0 * v0.z; aw += w0 * v0.w;
        ax += w1 * v1.x; ay += w1 * v1.y; az += w1 * v1.z; aw += w1 * v1.w;
    }
    if (p < e) {
        int   c = g_colS[p];
        float w = g_wS[p];
        float4 v = T4[(size_t)c * 32 + lane];
        ax += w * v.x; ay += w * v.y; az += w * v.z; aw += w * v.w;
    }

    float4 o;
    o.x = fmaxf(ax, 0.f); o.y = fmaxf(ay, 0.f);
    o.z = fmaxf(az, 0.f); o.w = fmaxf(aw, 0.f);
    ((float4*)O)[(size_t)warp * 32 + lane] = o;
}

// ---------------- launch -----------------------------------------------------
extern "C" void kernel_launch(void* const* d_in, const int* in_sizes, int n_in,
                              void* d_out, int out_size)
{
    const float* x    = (const float*)d_in[0];
    const int*   erow = (const int*)  d_in[1];
    const int*   ecol = (const int*)  d_in[2];
    const float* ew   = (const float*)d_in[3];
    const float* w1   = (const float*)d_in[4];
    const float* w2   = (const float*)d_in[5];
    const float* w3   = (const float*)d_in[6];
    float* out = (float*)d_out;

    const int N = in_sizes[0] / FDIM;   // 100000
    const int E = in_sizes[1];          // 1600000

    // scratch addresses (pure lookups; capture-safe, no allocation)
    float *dT = nullptr, *dH = nullptr;
    cudaGetSymbolAddress((void**)&dT, g_T);
    cudaGetSymbolAddress((void**)&dH, g_H);

    cudaFuncSetAttribute(k_gemm, cudaFuncAttributeMaxDynamicSharedMemorySize,
                         GEMM_SMEM_BYTES);

    // ---- build CSR (once per call; reused by all 3 layers) ----
    k_zero_cursor<<<(N + 255) / 256, 256>>>(N);
    k_hist<<<(E + 255) / 256, 256>>>(erow, E);
    int nb = (N + 1023) / 1024;
    k_scan1<<<nb, 1024>>>(N);
    k_scan2<<<1, 32>>>(nb);
    k_scan3<<<nb, 1024>>>(N, E);
    k_scatter<<<(E + 255) / 256, 256>>>(erow, ecol, ew, E);

    const int gemm_grid = (N + GEMM_BM - 1) / GEMM_BM;
    const int spmm_grid = (N + 7) / 8;   // 8 warps (256 thr) per block, warp/row

    // layer 1: T = X @ W1 ; H = relu(A*T)
    k_gemm<<<gemm_grid, GEMM_THREADS, GEMM_SMEM_BYTES>>>(x, w1, dT, N);
    k_spmm_relu<<<spmm_grid, 256>>>(dT, dH, N);
    // layer 2: T = H @ W2 ; H = relu(A*T)
    k_gemm<<<gemm_grid, GEMM_THREADS, GEMM_SMEM_BYTES>>>(dH, w2, dT, N);
    k_spmm_relu<<<spmm_grid, 256>>>(dT, dH, N);
    // layer 3: T = H @ W3 ; out = relu(A*T)
    k_gemm<<<gemm_grid, GEMM_THREADS, GEMM_SMEM_BYTES>>>(dH, w3, dT, N);
    k_spmm_relu<<<spmm_grid, 256>>>(dT, out, N);
}

// round 14
// speedup vs baseline: 1.1178x; 1.1178x over previous
#include <cuda_runtime.h>
#include <cuda_bf16.h>
#include <cstdint>

// Problem constants (fixed by the reference)
#define NMAX 100000
#define EMAX 1600000
#define FDIM 128

// ---------------- scratch (static device globals; no runtime allocation) ----
__device__ float g_T[(size_t)NMAX * FDIM];   // GEMM output per layer
__device__ float g_H[(size_t)NMAX * FDIM];   // layer activations
__device__ int   g_rowptr[NMAX + 1];
__device__ int   g_cursor[NMAX];
__device__ int   g_colS[EMAX];
__device__ float g_wS[EMAX];
__device__ int   g_bsum[256];

// ---------------- CSR build --------------------------------------------------
__global__ void k_zero_cursor(int n) {
    int i = blockIdx.x * blockDim.x + threadIdx.x;
    if (i < n) g_cursor[i] = 0;
}

__global__ void k_hist(const int* __restrict__ erow, int E) {
    int e = blockIdx.x * blockDim.x + threadIdx.x;
    if (e < E) atomicAdd(&g_cursor[erow[e]], 1);
}

__global__ void k_scan1(int n) {
    __shared__ int s[1024];
    int i = blockIdx.x * 1024 + threadIdx.x;
    int v = (i < n) ? g_cursor[i] : 0;
    s[threadIdx.x] = v;
    __syncthreads();
#pragma unroll
    for (int off = 1; off < 1024; off <<= 1) {
        int t = 0;
        if ((int)threadIdx.x >= off) t = s[threadIdx.x - off];
        __syncthreads();
        s[threadIdx.x] += t;
        __syncthreads();
    }
    if (i < n) g_rowptr[i] = s[threadIdx.x] - v;
    if (threadIdx.x == 1023) g_bsum[blockIdx.x] = s[1023];
}

__global__ void k_scan2(int nb) {
    if (threadIdx.x == 0 && blockIdx.x == 0) {
        int acc = 0;
        for (int b = 0; b < nb; b++) { int t = g_bsum[b]; g_bsum[b] = acc; acc += t; }
    }
}

__global__ void k_scan3(int n, int E) {
    int i = blockIdx.x * 1024 + threadIdx.x;
    if (i < n) {
        int rp = g_rowptr[i] + g_bsum[blockIdx.x];
        g_rowptr[i] = rp;
        g_cursor[i] = rp;
    }
    if (blockIdx.x == 0 && threadIdx.x == 0) g_rowptr[n] = E;
}

__global__ void k_scatter(const int* __restrict__ erow, const int* __restrict__ ecol,
                          const float* __restrict__ ew, int E) {
    int e = blockIdx.x * blockDim.x + threadIdx.x;
    if (e < E) {
        int r = erow[e];
        int p = atomicAdd(&g_cursor[r], 1);
        g_colS[p] = ecol[e];
        g_wS[p]   = ew[e];
    }
}

// ---------------- GEMM: C[N,128] = A[N,128] @ W[128,128] ---------------------
// bf16-split (3-term) tensor-core GEMM via mma.sync.m16n8k16.
// A = A_hi + A_lo (bf16 each), W likewise; C = Ah*Wh + Ah*Wl + Al*Wh (fp32 acc).
// CTA: 128 rows x 128 cols, 256 threads (8 warps, one m16 row-stripe per warp).
#define GT 256
#define GBM 128
#define LDA 136   // bf16 per smem row (128 + 8 pad) -> conflict-free frag loads
#define GEMM_SMEM_BYTES (4 * GBM * LDA * 2)   // Ah, Al, Bh, Bl = 139264 B

__device__ __forceinline__ void mma16816(float* c, const uint32_t* a,
                                         uint32_t b0, uint32_t b1) {
    asm volatile(
        "mma.sync.aligned.m16n8k16.row.col.f32.bf16.bf16.f32 "
        "{%0,%1,%2,%3}, {%4,%5,%6,%7}, {%8,%9}, {%0,%1,%2,%3};\n"
        : "+f"(c[0]), "+f"(c[1]), "+f"(c[2]), "+f"(c[3])
        : "r"(a[0]), "r"(a[1]), "r"(a[2]), "r"(a[3]), "r"(b0), "r"(b1));
}

__global__ __launch_bounds__(GT) void k_gemm_mma(
    const float* __restrict__ A, const float* __restrict__ W,
    float* __restrict__ C, int N)
{
    extern __shared__ __nv_bfloat16 sm[];
    __nv_bfloat16* Ah = sm;                    // [128][LDA]  (row m, k contig)
    __nv_bfloat16* Al = Ah + GBM * LDA;
    __nv_bfloat16* Bh = Al + GBM * LDA;        // [128][LDA]  (row n, k contig)
    __nv_bfloat16* Bl = Bh + 128 * LDA;

    const int tid = threadIdx.x;
    const int m_base = blockIdx.x * GBM;

    // B: Bs[n][k] = W[k][n] (transpose) + hi/lo split. Coalesced gmem reads.
    for (int i = tid; i < 128 * 128; i += GT) {
        int k = i >> 7, n = i & 127;
        float w = W[i];
        __nv_bfloat16 hi = __float2bfloat16(w);
        Bh[n * LDA + k] = hi;
        Bl[n * LDA + k] = __float2bfloat16(w - __bfloat162float(hi));
    }
    // A tile: float4 loads, hi/lo split, guarded
    {
        const float4* A4 = (const float4*)A;
        for (int i = tid; i < GBM * 32; i += GT) {
            int r = i >> 5, kq = i & 31;
            float4 v = make_float4(0.f, 0.f, 0.f, 0.f);
            if (m_base + r < N) v = A4[(size_t)(m_base + r) * 32 + kq];
            float vv[4] = {v.x, v.y, v.z, v.w};
            int kk = kq * 4;
#pragma unroll
            for (int j = 0; j < 4; j++) {
                __nv_bfloat16 hi = __float2bfloat16(vv[j]);
                Ah[r * LDA + kk + j] = hi;
                Al[r * LDA + kk + j] = __float2bfloat16(vv[j] - __bfloat162float(hi));
            }
        }
    }
    __syncthreads();

    const int warp = tid >> 5, lane = tid & 31;
    const int m0 = warp * 16;
    const int qr = lane >> 2;        // 0..7 (group)
    const int qk = (lane & 3) * 2;   // 0,2,4,6

    float acc[64];
#pragma unroll
    for (int i = 0; i < 64; i++) acc[i] = 0.f;

#pragma unroll
    for (int ks = 0; ks < 8; ks++) {
        const int k0 = ks * 16;
        uint32_t ah[4], al[4];
        {
            const __nv_bfloat16* p0 = Ah + (m0 + qr) * LDA + k0 + qk;
            const __nv_bfloat16* p1 = Ah + (m0 + qr + 8) * LDA + k0 + qk;
            ah[0] = *(const uint32_t*)p0;
            ah[1] = *(const uint32_t*)p1;
            ah[2] = *(const uint32_t*)(p0 + 8);
            ah[3] = *(const uint32_t*)(p1 + 8);
            const __nv_bfloat16* q0 = Al + (m0 + qr) * LDA + k0 + qk;
            const __nv_bfloat16* q1 = Al + (m0 + qr + 8) * LDA + k0 + qk;
            al[0] = *(const uint32_t*)q0;
            al[1] = *(const uint32_t*)q1;
            al[2] = *(const uint32_t*)(q0 + 8);
            al[3] = *(const uint32_t*)(q1 + 8);
        }
#pragma unroll
        for (int nt = 0; nt < 16; nt++) {
            const int n = nt * 8 + qr;
            uint32_t bh0 = *(const uint32_t*)(Bh + n * LDA + k0 + qk);
            uint32_t bh1 = *(const uint32_t*)(Bh + n * LDA + k0 + qk + 8);
            uint32_t bl0 = *(const uint32_t*)(Bl + n * LDA + k0 + qk);
            uint32_t bl1 = *(const uint32_t*)(Bl + n * LDA + k0 + qk + 8);
            float* c = acc + nt * 4;
            mma16816(c, ah, bh0, bh1);   // hi * hi
            mma16816(c, ah, bl0, bl1);   // hi * lo
            mma16816(c, al, bh0, bh1);   // lo * hi
        }
    }

    // epilogue: c0,c1 -> (row qr, col qk..qk+1); c2,c3 -> row qr+8
#pragma unroll
    for (int nt = 0; nt < 16; nt++) {
        const int col = nt * 8 + qk;
        const int r0 = m_base + m0 + qr;
        const int r1 = r0 + 8;
        if (r0 < N)
            *(float2*)(C + (size_t)r0 * 128 + col) = make_float2(acc[nt * 4 + 0], acc[nt * 4 + 1]);
        if (r1 < N)
            *(float2*)(C + (size_t)r1 * 128 + col) = make_float2(acc[nt * 4 + 2], acc[nt * 4 + 3]);
    }
}

// ---------------- SpMM (CSR) + ReLU: O[r] = relu(sum_e w_e * T[col_e]) ------
// warp per row, lane handles one float4 (128 floats / 32 lanes)
__global__ __launch_bounds__(256) void k_spmm_relu(
    const float* __restrict__ T, float* __restrict__ O, int N)
{
    int warp = (blockIdx.x * blockDim.x + threadIdx.x) >> 5;
    int lane = threadIdx.x & 31;
    if (warp >= N) return;

    int s = g_rowptr[warp];
    int e = g_rowptr[warp + 1];

    float ax = 0.f, ay = 0.f, az = 0.f, aw = 0.f;
    const float4* T4 = (const float4*)T;

    int p = s;
#pragma unroll 1
    for (; p + 4 <= e; p += 4) {
        int   c0 = __ldg(&g_colS[p]),     c1 = __ldg(&g_colS[p + 1]);
        int   c2 = __ldg(&g_colS[p + 2]), c3 = __ldg(&g_colS[p + 3]);
        float w0 = __ldg(&g_wS[p]),       w1 = __ldg(&g_wS[p + 1]);
        float w2 = __ldg(&g_wS[p + 2]),   w3 = __ldg(&g_wS[p + 3]);
        float4 v0 = T4[(size_t)c0 * 32 + lane];
        float4 v1 = T4[(size_t)c1 * 32 + lane];
        float4 v2 = T4[(size_t)c2 * 32 + lane];
        float4 v3 = T4[(size_t)c3 * 32 + lane];
        ax += w0 * v0.x; ay += w0 * v0.y; az += w0 * v0.z; aw += w0 * v0.w;
        ax += w1 * v1.x; ay += w1 * v1.y; az += w1 * v1.z; aw += w1 * v1.w;
        ax += w2 * v2.x; ay += w2 * v2.y; az += w2 * v2.z; aw += w2 * v2.w;
        ax += w3 * v3.x; ay += w3 * v3.y; az += w3 * v3.z; aw += w3 * v3.w;
    }
    for (; p < e; p++) {
        int   c = g_colS[p];
        float w = g_wS[p];
        float4 v = T4[(size_t)c * 32 + lane];
        ax += w * v.x; ay += w * v.y; az += w * v.z; aw += w * v.w;
    }

    float4 o;
    o.x = fmaxf(ax, 0.f); o.y = fmaxf(ay, 0.f);
    o.z = fmaxf(az, 0.f); o.w = fmaxf(aw, 0.f);
    ((float4*)O)[(size_t)warp * 32 + lane] = o;
}

// ---------------- launch -----------------------------------------------------
extern "C" void kernel_launch(void* const* d_in, const int* in_sizes, int n_in,
                              void* d_out, int out_size)
{
    const float* x    = (const float*)d_in[0];
    const int*   erow = (const int*)  d_in[1];
    const int*   ecol = (const int*)  d_in[2];
    const float* ew   = (const float*)d_in[3];
    const float* w1   = (const float*)d_in[4];
    const float* w2   = (const float*)d_in[5];
    const float* w3   = (const float*)d_in[6];
    float* out = (float*)d_out;

    const int N = in_sizes[0] / FDIM;   // 100000
    const int E = in_sizes[1];          // 1600000

    float *dT = nullptr, *dH = nullptr;
    cudaGetSymbolAddress((void**)&dT, g_T);
    cudaGetSymbolAddress((void**)&dH, g_H);

    cudaFuncSetAttribute(k_gemm_mma, cudaFuncAttributeMaxDynamicSharedMemorySize,
                         GEMM_SMEM_BYTES);

    // ---- build CSR (once per call; reused by all 3 layers) ----
    k_zero_cursor<<<(N + 255) / 256, 256>>>(N);
    k_hist<<<(E + 255) / 256, 256>>>(erow, E);
    int nb = (N + 1023) / 1024;
    k_scan1<<<nb, 1024>>>(N);
    k_scan2<<<1, 32>>>(nb);
    k_scan3<<<nb, 1024>>>(N, E);
    k_scatter<<<(E + 255) / 256, 256>>>(erow, ecol, ew, E);

    const int gemm_grid = (N + GBM - 1) / GBM;
    const int spmm_grid = (N + 7) / 8;

    // layer 1
    k_gemm_mma<<<gemm_grid, GT, GEMM_SMEM_BYTES>>>(x, w1, dT, N);
    k_spmm_relu<<<spmm_grid, 256>>>(dT, dH, N);
    // layer 2
    k_gemm_mma<<<gemm_grid, GT, GEMM_SMEM_BYTES>>>(dH, w2, dT, N);
    k_spmm_relu<<<spmm_grid, 256>>>(dT, dH, N);
    // layer 3
    k_gemm_mma<<<gemm_grid, GT, GEMM_SMEM_BYTES>>>(dH, w3, dT, N);
    k_spmm_relu<<<spmm_grid, 256>>>(dT, out, N);
}

// round 15
// speedup vs baseline: 1.5223x; 1.3618x over previous
#include <cuda_runtime.h>
#include <cuda_bf16.h>
#include <cstdint>

// Problem constants (fixed by the reference)
#define NMAX 100000
#define EMAX 1600000
#define FDIM 128

// ---------------- scratch (static device globals; no runtime allocation) ----
__device__ float          g_T[(size_t)NMAX * FDIM];   // GEMM output (gathered by SpMM)
__device__ __nv_bfloat16  g_Ah[(size_t)NMAX * FDIM];  // GEMM input, hi part
__device__ __nv_bfloat16  g_Al[(size_t)NMAX * FDIM];  // GEMM input, lo part
__device__ __nv_bfloat16  g_WhT[3 * 128 * 128];       // W^T hi, [layer][n][k]
__device__ __nv_bfloat16  g_WlT[3 * 128 * 128];       // W^T lo
__device__ int   g_rowptr[NMAX + 1];
__device__ int   g_cursor[NMAX];
__device__ int2  g_edge[EMAX];                        // {col, weight-bits}
__device__ int   g_bsum[256];

// ---------------- hi/lo split helpers ---------------------------------------
__device__ __forceinline__ void split2(float a, float b, uint32_t& hi, uint32_t& lo) {
    __nv_bfloat16 ha = __float2bfloat16(a);
    __nv_bfloat16 hb = __float2bfloat16(b);
    __nv_bfloat162 h; h.x = ha; h.y = hb;
    __nv_bfloat162 l;
    l.x = __float2bfloat16(a - __bfloat162float(ha));
    l.y = __float2bfloat16(b - __bfloat162float(hb));
    hi = *(uint32_t*)&h;
    lo = *(uint32_t*)&l;
}

// ---------------- weight pre-split (once; 3 layers) --------------------------
// WhT[n][k] = bf16_hi(W[k][n]); WlT = residual. grid (64,3), 256 thr.
__global__ void k_split_w(const float* __restrict__ w1, const float* __restrict__ w2,
                          const float* __restrict__ w3) {
    const float* W = (blockIdx.y == 0) ? w1 : (blockIdx.y == 1) ? w2 : w3;
    __nv_bfloat16* Wh = g_WhT + blockIdx.y * 16384;
    __nv_bfloat16* Wl = g_WlT + blockIdx.y * 16384;
    int i = blockIdx.x * 256 + threadIdx.x;   // i = n*128 + k
    int n = i >> 7, k = i & 127;
    float v = W[k * 128 + n];
    __nv_bfloat16 hi = __float2bfloat16(v);
    Wh[i] = hi;
    Wl[i] = __float2bfloat16(v - __bfloat162float(hi));
}

// ---------------- layer-1 input split ----------------------------------------
__global__ void k_split_x(const float* __restrict__ X, int n4) {
    int i = blockIdx.x * 256 + threadIdx.x;
    if (i >= n4) return;
    float4 v = ((const float4*)X)[i];
    uint2 h, l;
    split2(v.x, v.y, h.x, l.x);
    split2(v.z, v.w, h.y, l.y);
    ((uint2*)g_Ah)[i] = h;
    ((uint2*)g_Al)[i] = l;
}

// ---------------- CSR build --------------------------------------------------
__global__ void k_hist(const int* __restrict__ erow, int E) {
    int e = blockIdx.x * blockDim.x + threadIdx.x;
    if (e < E) atomicAdd(&g_cursor[erow[e]], 1);
}

__global__ void k_scan1(int n) {
    __shared__ int s[1024];
    int i = blockIdx.x * 1024 + threadIdx.x;
    int v = (i < n) ? g_cursor[i] : 0;
    s[threadIdx.x] = v;
    __syncthreads();
#pragma unroll
    for (int off = 1; off < 1024; off <<= 1) {
        int t = 0;
        if ((int)threadIdx.x >= off) t = s[threadIdx.x - off];
        __syncthreads();
        s[threadIdx.x] += t;
        __syncthreads();
    }
    if (i < n) g_rowptr[i] = s[threadIdx.x] - v;
    if (threadIdx.x == 1023) g_bsum[blockIdx.x] = s[1023];
}

// parallel scan of <=128 block sums (nb = 98 here)
__global__ void k_scan2(int nb) {
    __shared__ int s[128];
    int t = threadIdx.x;
    int v = (t < nb) ? g_bsum[t] : 0;
    s[t] = v;
    __syncthreads();
#pragma unroll
    for (int off = 1; off < 128; off <<= 1) {
        int u = (t >= off) ? s[t - off] : 0;
        __syncthreads();
        s[t] += u;
        __syncthreads();
    }
    if (t < nb) g_bsum[t] = s[t] - v;   // exclusive
}

__global__ void k_scan3(int n, int E) {
    int i = blockIdx.x * 1024 + threadIdx.x;
    if (i < n) {
        int rp = g_rowptr[i] + g_bsum[blockIdx.x];
        g_rowptr[i] = rp;
        g_cursor[i] = rp;
    }
    if (blockIdx.x == 0 && threadIdx.x == 0) g_rowptr[n] = E;
}

__global__ void k_scatter(const int* __restrict__ erow, const int* __restrict__ ecol,
                          const float* __restrict__ ew, int E) {
    int e = blockIdx.x * blockDim.x + threadIdx.x;
    if (e < E) {
        int p = atomicAdd(&g_cursor[erow[e]], 1);
        g_edge[p] = make_int2(ecol[e], __float_as_int(ew[e]));
    }
}

// ---------------- GEMM: T[N,128] = A[N,128] @ W[128,128] ---------------------
// bf16-split 3-term tensor-core GEMM, inputs PRE-SPLIT (Ah/Al, WhT/WlT bf16).
// CTA: 128 rows, 256 threads (8 warps x m16 stripe). No conversions in-kernel.
#define GT 256
#define GBM 128
#define LDA 136   // bf16 per smem row (128 + 8 pad) -> conflict-free frag loads
#define GEMM_SMEM_BYTES (4 * 128 * LDA * 2)   // 139264 B

__device__ __forceinline__ void mma16816(float* c, const uint32_t* a,
                                         uint32_t b0, uint32_t b1) {
    asm volatile(
        "mma.sync.aligned.m16n8k16.row.col.f32.bf16.bf16.f32 "
        "{%0,%1,%2,%3}, {%4,%5,%6,%7}, {%8,%9}, {%0,%1,%2,%3};\n"
        : "+f"(c[0]), "+f"(c[1]), "+f"(c[2]), "+f"(c[3])
        : "r"(a[0]), "r"(a[1]), "r"(a[2]), "r"(a[3]), "r"(b0), "r"(b1));
}

__global__ __launch_bounds__(GT) void k_gemm_mma(
    const __nv_bfloat16* __restrict__ Agh, const __nv_bfloat16* __restrict__ Agl,
    const __nv_bfloat16* __restrict__ Wh,  const __nv_bfloat16* __restrict__ Wl,
    float* __restrict__ C, int N)
{
    extern __shared__ __nv_bfloat16 sm[];
    __nv_bfloat16* Ah = sm;                  // [128][LDA]
    __nv_bfloat16* Al = Ah + 128 * LDA;
    __nv_bfloat16* Bh = Al + 128 * LDA;      // [n][LDA] (k contig)
    __nv_bfloat16* Bl = Bh + 128 * LDA;

    const int tid = threadIdx.x;
    const int m_base = blockIdx.x * GBM;

    // coalesced uint4 tile loads (8 bf16 each); 8 iters per array per thread
    {
        const uint4* A4h = (const uint4*)Agh;
        const uint4* A4l = (const uint4*)Agl;
        const uint4* B4h = (const uint4*)Wh;
        const uint4* B4l = (const uint4*)Wl;
        const uint4 z = make_uint4(0, 0, 0, 0);
#pragma unroll
        for (int it = 0; it < 8; it++) {
            int i = tid + it * GT;            // 0..2047
            int r = i >> 4, kq = i & 15;      // row, 8-bf16 chunk
            bool ok = (m_base + r) < N;
            uint4 va = ok ? A4h[(size_t)(m_base + r) * 16 + kq] : z;
            uint4 vb = ok ? A4l[(size_t)(m_base + r) * 16 + kq] : z;
            *(uint4*)(Ah + r * LDA + kq * 8) = va;
            *(uint4*)(Al + r * LDA + kq * 8) = vb;
            *(uint4*)(Bh + r * LDA + kq * 8) = B4h[i];
            *(uint4*)(Bl + r * LDA + kq * 8) = B4l[i];
        }
    }
    __syncthreads();

    const int warp = tid >> 5, lane = tid & 31;
    const int m0 = warp * 16;
    const int qr = lane >> 2;        // 0..7
    const int qk = (lane & 3) * 2;   // 0,2,4,6

    float acc[64];
#pragma unroll
    for (int i = 0; i < 64; i++) acc[i] = 0.f;

#pragma unroll
    for (int ks = 0; ks < 8; ks++) {
        const int k0 = ks * 16;
        uint32_t ah[4], al[4];
        {
            const __nv_bfloat16* p0 = Ah + (m0 + qr) * LDA + k0 + qk;
            const __nv_bfloat16* p1 = Ah + (m0 + qr + 8) * LDA + k0 + qk;
            ah[0] = *(const uint32_t*)p0;
            ah[1] = *(const uint32_t*)p1;
            ah[2] = *(const uint32_t*)(p0 + 8);
            ah[3] = *(const uint32_t*)(p1 + 8);
            const __nv_bfloat16* q0 = Al + (m0 + qr) * LDA + k0 + qk;
            const __nv_bfloat16* q1 = Al + (m0 + qr + 8) * LDA + k0 + qk;
            al[0] = *(const uint32_t*)q0;
            al[1] = *(const uint32_t*)q1;
            al[2] = *(const uint32_t*)(q0 + 8);
            al[3] = *(const uint32_t*)(q1 + 8);
        }
#pragma unroll
        for (int nt = 0; nt < 16; nt++) {
            const int n = nt * 8 + qr;
            uint32_t bh0 = *(const uint32_t*)(Bh + n * LDA + k0 + qk);
            uint32_t bh1 = *(const uint32_t*)(Bh + n * LDA + k0 + qk + 8);
            uint32_t bl0 = *(const uint32_t*)(Bl + n * LDA + k0 + qk);
            uint32_t bl1 = *(const uint32_t*)(Bl + n * LDA + k0 + qk + 8);
            float* c = acc + nt * 4;
            mma16816(c, ah, bh0, bh1);   // hi*hi
            mma16816(c, ah, bl0, bl1);   // hi*lo
            mma16816(c, al, bh0, bh1);   // lo*hi
        }
    }

#pragma unroll
    for (int nt = 0; nt < 16; nt++) {
        const int col = nt * 8 + qk;
        const int r0 = m_base + m0 + qr;
        const int r1 = r0 + 8;
        if (r0 < N)
            *(float2*)(C + (size_t)r0 * 128 + col) = make_float2(acc[nt * 4 + 0], acc[nt * 4 + 1]);
        if (r1 < N)
            *(float2*)(C + (size_t)r1 * 128 + col) = make_float2(acc[nt * 4 + 2], acc[nt * 4 + 3]);
    }
}

// ---------------- SpMM (CSR) + ReLU ------------------------------------------
// warp/row, lane/float4. SPLIT=1: write bf16 hi/lo (feeds next GEMM);
// SPLIT=0: write fp32 (final output).
template <int SPLIT>
__global__ __launch_bounds__(256) void k_spmm_relu(
    const float* __restrict__ T, float* __restrict__ O, int N)
{
    int warp = (blockIdx.x * blockDim.x + threadIdx.x) >> 5;
    int lane = threadIdx.x & 31;
    if (warp >= N) return;

    int s = g_rowptr[warp];
    int e = g_rowptr[warp + 1];

    float ax = 0.f, ay = 0.f, az = 0.f, aw = 0.f;
    const float4* T4 = (const float4*)T;

    int p = s;
#pragma unroll 1
    for (; p + 4 <= e; p += 4) {
        int2 e0 = __ldg(&g_edge[p]),     e1 = __ldg(&g_edge[p + 1]);
        int2 e2 = __ldg(&g_edge[p + 2]), e3 = __ldg(&g_edge[p + 3]);
        float4 v0 = T4[(size_t)e0.x * 32 + lane];
        float4 v1 = T4[(size_t)e1.x * 32 + lane];
        float4 v2 = T4[(size_t)e2.x * 32 + lane];
        float4 v3 = T4[(size_t)e3.x * 32 + lane];
        float w0 = __int_as_float(e0.y), w1 = __int_as_float(e1.y);
        float w2 = __int_as_float(e2.y), w3 = __int_as_float(e3.y);
        ax += w0 * v0.x; ay += w0 * v0.y; az += w0 * v0.z; aw += w0 * v0.w;
        ax += w1 * v1.x; ay += w1 * v1.y; az += w1 * v1.z; aw += w1 * v1.w;
        ax += w2 * v2.x; ay += w2 * v2.y; az += w2 * v2.z; aw += w2 * v2.w;
        ax += w3 * v3.x; ay += w3 * v3.y; az += w3 * v3.z; aw += w3 * v3.w;
    }
    for (; p < e; p++) {
        int2 ed = __ldg(&g_edge[p]);
        float w = __int_as_float(ed.y);
        float4 v = T4[(size_t)ed.x * 32 + lane];
        ax += w * v.x; ay += w * v.y; az += w * v.z; aw += w * v.w;
    }

    ax = fmaxf(ax, 0.f); ay = fmaxf(ay, 0.f);
    az = fmaxf(az, 0.f); aw = fmaxf(aw, 0.f);

    if (SPLIT) {
        uint2 h, l;
        split2(ax, ay, h.x, l.x);
        split2(az, aw, h.y, l.y);
        ((uint2*)g_Ah)[(size_t)warp * 32 + lane] = h;
        ((uint2*)g_Al)[(size_t)warp * 32 + lane] = l;
    } else {
        ((float4*)O)[(size_t)warp * 32 + lane] =
            make_float4(ax, ay, az, aw);
    }
}

// ---------------- launch -----------------------------------------------------
extern "C" void kernel_launch(void* const* d_in, const int* in_sizes, int n_in,
                              void* d_out, int out_size)
{
    const float* x    = (const float*)d_in[0];
    const int*   erow = (const int*)  d_in[1];
    const int*   ecol = (const int*)  d_in[2];
    const float* ew   = (const float*)d_in[3];
    const float* w1   = (const float*)d_in[4];
    const float* w2   = (const float*)d_in[5];
    const float* w3   = (const float*)d_in[6];
    float* out = (float*)d_out;

    const int N = in_sizes[0] / FDIM;   // 100000
    const int E = in_sizes[1];          // 1600000

    float *dT = nullptr;
    __nv_bfloat16 *dAh = nullptr, *dAl = nullptr, *dWh = nullptr, *dWl = nullptr;
    int* dCursor = nullptr;
    cudaGetSymbolAddress((void**)&dT, g_T);
    cudaGetSymbolAddress((void**)&dAh, g_Ah);
    cudaGetSymbolAddress((void**)&dAl, g_Al);
    cudaGetSymbolAddress((void**)&dWh, g_WhT);
    cudaGetSymbolAddress((void**)&dWl, g_WlT);
    cudaGetSymbolAddress((void**)&dCursor, g_cursor);

    cudaFuncSetAttribute(k_gemm_mma, cudaFuncAttributeMaxDynamicSharedMemorySize,
                         GEMM_SMEM_BYTES);

    // ---- pre-splits + CSR build ----
    k_split_w<<<dim3(64, 3), 256>>>(w1, w2, w3);
    k_split_x<<<(N * 32 + 255) / 256, 256>>>(x, N * 32);
    cudaMemsetAsync(dCursor, 0, (size_t)N * sizeof(int));
    k_hist<<<(E + 255) / 256, 256>>>(erow, E);
    int nb = (N + 1023) / 1024;
    k_scan1<<<nb, 1024>>>(N);
    k_scan2<<<1, 128>>>(nb);
    k_scan3<<<nb, 1024>>>(N, E);
    k_scatter<<<(E + 255) / 256, 256>>>(erow, ecol, ew, E);

    const int gemm_grid = (N + GBM - 1) / GBM;
    const int spmm_grid = (N + 7) / 8;

    // layer 1
    k_gemm_mma<<<gemm_grid, GT, GEMM_SMEM_BYTES>>>(dAh, dAl, dWh, dWl, dT, N);
    k_spmm_relu<1><<<spmm_grid, 256>>>(dT, nullptr, N);
    // layer 2
    k_gemm_mma<<<gemm_grid, GT, GEMM_SMEM_BYTES>>>(dAh, dAl, dWh + 16384, dWl + 16384, dT, N);
    k_spmm_relu<1><<<spmm_grid, 256>>>(dT, nullptr, N);
    // layer 3
    k_gemm_mma<<<gemm_grid, GT, GEMM_SMEM_BYTES>>>(dAh, dAl, dWh + 32768, dWl + 32768, dT, N);
    k_spmm_relu<0><<<spmm_grid, 256>>>(dT, out, N);
}

// round 16
// speedup vs baseline: 1.7887x; 1.1751x over previous
#include <cuda_runtime.h>
#include <cuda_bf16.h>
#include <cuda_fp16.h>
#include <cstdint>

// Problem constants (fixed by the reference)
#define NMAX 100000
#define EMAX 1600000
#define FDIM 128

// ---------------- scratch (static device globals; no runtime allocation) ----
__device__ __half          g_T[(size_t)NMAX * FDIM];   // GEMM output (fp16, gathered)
__device__ __nv_bfloat16   g_Ah[(size_t)NMAX * FDIM];  // GEMM input, hi part
__device__ __nv_bfloat16   g_Al[(size_t)NMAX * FDIM];  // GEMM input, lo part
__device__ __nv_bfloat16   g_WhT[3 * 128 * 128];       // W^T hi, [layer][n][k]
__device__ __nv_bfloat16   g_WlT[3 * 128 * 128];       // W^T lo
__device__ int   g_rowptr[NMAX + 1];
__device__ int   g_cursor[NMAX];
__device__ int2  g_edge[EMAX];                         // {col, weight-bits}
__device__ int   g_bsum[256];

// ---------------- hi/lo split helpers ---------------------------------------
__device__ __forceinline__ void split2(float a, float b, uint32_t& hi, uint32_t& lo) {
    __nv_bfloat16 ha = __float2bfloat16(a);
    __nv_bfloat16 hb = __float2bfloat16(b);
    __nv_bfloat162 h; h.x = ha; h.y = hb;
    __nv_bfloat162 l;
    l.x = __float2bfloat16(a - __bfloat162float(ha));
    l.y = __float2bfloat16(b - __bfloat162float(hb));
    hi = *(uint32_t*)&h;
    lo = *(uint32_t*)&l;
}

// ---------------- weight pre-split (once; 3 layers) --------------------------
__global__ void k_split_w(const float* __restrict__ w1, const float* __restrict__ w2,
                          const float* __restrict__ w3) {
    const float* W = (blockIdx.y == 0) ? w1 : (blockIdx.y == 1) ? w2 : w3;
    __nv_bfloat16* Wh = g_WhT + blockIdx.y * 16384;
    __nv_bfloat16* Wl = g_WlT + blockIdx.y * 16384;
    int i = blockIdx.x * 256 + threadIdx.x;   // i = n*128 + k
    int n = i >> 7, k = i & 127;
    float v = W[k * 128 + n];
    __nv_bfloat16 hi = __float2bfloat16(v);
    Wh[i] = hi;
    Wl[i] = __float2bfloat16(v - __bfloat162float(hi));
}

// ---------------- layer-1 input split ----------------------------------------
__global__ void k_split_x(const float* __restrict__ X, int n4) {
    int i = blockIdx.x * 256 + threadIdx.x;
    if (i >= n4) return;
    float4 v = ((const float4*)X)[i];
    uint2 h, l;
    split2(v.x, v.y, h.x, l.x);
    split2(v.z, v.w, h.y, l.y);
    ((uint2*)g_Ah)[i] = h;
    ((uint2*)g_Al)[i] = l;
}

// ---------------- CSR build --------------------------------------------------
__global__ void k_hist(const int* __restrict__ erow, int E) {
    int e = blockIdx.x * blockDim.x + threadIdx.x;
    if (e < E) atomicAdd(&g_cursor[erow[e]], 1);
}

__global__ void k_scan1(int n) {
    __shared__ int s[1024];
    int i = blockIdx.x * 1024 + threadIdx.x;
    int v = (i < n) ? g_cursor[i] : 0;
    s[threadIdx.x] = v;
    __syncthreads();
#pragma unroll
    for (int off = 1; off < 1024; off <<= 1) {
        int t = 0;
        if ((int)threadIdx.x >= off) t = s[threadIdx.x - off];
        __syncthreads();
        s[threadIdx.x] += t;
        __syncthreads();
    }
    if (i < n) g_rowptr[i] = s[threadIdx.x] - v;
    if (threadIdx.x == 1023) g_bsum[blockIdx.x] = s[1023];
}

__global__ void k_scan2(int nb) {
    __shared__ int s[128];
    int t = threadIdx.x;
    int v = (t < nb) ? g_bsum[t] : 0;
    s[t] = v;
    __syncthreads();
#pragma unroll
    for (int off = 1; off < 128; off <<= 1) {
        int u = (t >= off) ? s[t - off] : 0;
        __syncthreads();
        s[t] += u;
        __syncthreads();
    }
    if (t < nb) g_bsum[t] = s[t] - v;   // exclusive
}

__global__ void k_scan3(int n, int E) {
    int i = blockIdx.x * 1024 + threadIdx.x;
    if (i < n) {
        int rp = g_rowptr[i] + g_bsum[blockIdx.x];
        g_rowptr[i] = rp;
        g_cursor[i] = rp;
    }
    if (blockIdx.x == 0 && threadIdx.x == 0) g_rowptr[n] = E;
}

__global__ void k_scatter(const int* __restrict__ erow, const int* __restrict__ ecol,
                          const float* __restrict__ ew, int E) {
    int e = blockIdx.x * blockDim.x + threadIdx.x;
    if (e < E) {
        int p = atomicAdd(&g_cursor[erow[e]], 1);
        g_edge[p] = make_int2(ecol[e], __float_as_int(ew[e]));
    }
}

// ---------------- GEMM: T[N,128] = A[N,128] @ W[128,128] ---------------------
// bf16-split 3-term tensor-core GEMM, inputs PRE-SPLIT; fp16 output.
#define GT 256
#define GBM 128
#define LDA 136
#define GEMM_SMEM_BYTES (4 * 128 * LDA * 2)   // 139264 B

__device__ __forceinline__ void mma16816(float* c, const uint32_t* a,
                                         uint32_t b0, uint32_t b1) {
    asm volatile(
        "mma.sync.aligned.m16n8k16.row.col.f32.bf16.bf16.f32 "
        "{%0,%1,%2,%3}, {%4,%5,%6,%7}, {%8,%9}, {%0,%1,%2,%3};\n"
        : "+f"(c[0]), "+f"(c[1]), "+f"(c[2]), "+f"(c[3])
        : "r"(a[0]), "r"(a[1]), "r"(a[2]), "r"(a[3]), "r"(b0), "r"(b1));
}

__global__ __launch_bounds__(GT) void k_gemm_mma(
    const __nv_bfloat16* __restrict__ Agh, const __nv_bfloat16* __restrict__ Agl,
    const __nv_bfloat16* __restrict__ Wh,  const __nv_bfloat16* __restrict__ Wl,
    __half* __restrict__ C, int N)
{
    extern __shared__ __nv_bfloat16 sm[];
    __nv_bfloat16* Ah = sm;                  // [128][LDA]
    __nv_bfloat16* Al = Ah + 128 * LDA;
    __nv_bfloat16* Bh = Al + 128 * LDA;      // [n][LDA] (k contig)
    __nv_bfloat16* Bl = Bh + 128 * LDA;

    const int tid = threadIdx.x;
    const int m_base = blockIdx.x * GBM;

    {
        const uint4* A4h = (const uint4*)Agh;
        const uint4* A4l = (const uint4*)Agl;
        const uint4* B4h = (const uint4*)Wh;
        const uint4* B4l = (const uint4*)Wl;
        const uint4 z = make_uint4(0, 0, 0, 0);
#pragma unroll
        for (int it = 0; it < 8; it++) {
            int i = tid + it * GT;            // 0..2047
            int r = i >> 4, kq = i & 15;
            bool ok = (m_base + r) < N;
            uint4 va = ok ? A4h[(size_t)(m_base + r) * 16 + kq] : z;
            uint4 vb = ok ? A4l[(size_t)(m_base + r) * 16 + kq] : z;
            *(uint4*)(Ah + r * LDA + kq * 8) = va;
            *(uint4*)(Al + r * LDA + kq * 8) = vb;
            *(uint4*)(Bh + r * LDA + kq * 8) = B4h[i];
            *(uint4*)(Bl + r * LDA + kq * 8) = B4l[i];
        }
    }
    __syncthreads();

    const int warp = tid >> 5, lane = tid & 31;
    const int m0 = warp * 16;
    const int qr = lane >> 2;        // 0..7
    const int qk = (lane & 3) * 2;   // 0,2,4,6

    float acc[64];
#pragma unroll
    for (int i = 0; i < 64; i++) acc[i] = 0.f;

#pragma unroll
    for (int ks = 0; ks < 8; ks++) {
        const int k0 = ks * 16;
        uint32_t ah[4], al[4];
        {
            const __nv_bfloat16* p0 = Ah + (m0 + qr) * LDA + k0 + qk;
            const __nv_bfloat16* p1 = Ah + (m0 + qr + 8) * LDA + k0 + qk;
            ah[0] = *(const uint32_t*)p0;
            ah[1] = *(const uint32_t*)p1;
            ah[2] = *(const uint32_t*)(p0 + 8);
            ah[3] = *(const uint32_t*)(p1 + 8);
            const __nv_bfloat16* q0 = Al + (m0 + qr) * LDA + k0 + qk;
            const __nv_bfloat16* q1 = Al + (m0 + qr + 8) * LDA + k0 + qk;
            al[0] = *(const uint32_t*)q0;
            al[1] = *(const uint32_t*)q1;
            al[2] = *(const uint32_t*)(q0 + 8);
            al[3] = *(const uint32_t*)(q1 + 8);
        }
#pragma unroll
        for (int nt = 0; nt < 16; nt++) {
            const int n = nt * 8 + qr;
            uint32_t bh0 = *(const uint32_t*)(Bh + n * LDA + k0 + qk);
            uint32_t bh1 = *(const uint32_t*)(Bh + n * LDA + k0 + qk + 8);
            uint32_t bl0 = *(const uint32_t*)(Bl + n * LDA + k0 + qk);
            uint32_t bl1 = *(const uint32_t*)(Bl + n * LDA + k0 + qk + 8);
            float* c = acc + nt * 4;
            mma16816(c, ah, bh0, bh1);   // hi*hi
            mma16816(c, ah, bl0, bl1);   // hi*lo
            mma16816(c, al, bh0, bh1);   // lo*hi
        }
    }

    // epilogue: fp16 store. c0,c1 -> (row qr, cols qk,qk+1); c2,c3 -> row qr+8
#pragma unroll
    for (int nt = 0; nt < 16; nt++) {
        const int col = nt * 8 + qk;
        const int r0 = m_base + m0 + qr;
        const int r1 = r0 + 8;
        __half2 h0 = __floats2half2_rn(acc[nt * 4 + 0], acc[nt * 4 + 1]);
        __half2 h1 = __floats2half2_rn(acc[nt * 4 + 2], acc[nt * 4 + 3]);
        if (r0 < N) *(__half2*)(C + (size_t)r0 * 128 + col) = h0;
        if (r1 < N) *(__half2*)(C + (size_t)r1 * 128 + col) = h1;
    }
}

// ---------------- SpMM (CSR) + ReLU ------------------------------------------
// warp/row, lane handles 4 features (one uint2 = 4 fp16). fp32 accumulate.
// SPLIT=1: write bf16 hi/lo (feeds next GEMM); SPLIT=0: write fp32 output.
template <int SPLIT>
__global__ __launch_bounds__(256) void k_spmm_relu(
    const __half* __restrict__ T, float* __restrict__ O, int N)
{
    int warp = (blockIdx.x * blockDim.x + threadIdx.x) >> 5;
    int lane = threadIdx.x & 31;
    if (warp >= N) return;

    int s = g_rowptr[warp];
    int e = g_rowptr[warp + 1];

    float ax = 0.f, ay = 0.f, az = 0.f, aw = 0.f;
    const uint2* T2 = (const uint2*)T;   // index = row*32 + lane

    int p = s;
#pragma unroll 1
    for (; p + 4 <= e; p += 4) {
        int2 e0 = __ldg(&g_edge[p]),     e1 = __ldg(&g_edge[p + 1]);
        int2 e2 = __ldg(&g_edge[p + 2]), e3 = __ldg(&g_edge[p + 3]);
        uint2 u0 = __ldg(&T2[(size_t)e0.x * 32 + lane]);
        uint2 u1 = __ldg(&T2[(size_t)e1.x * 32 + lane]);
        uint2 u2 = __ldg(&T2[(size_t)e2.x * 32 + lane]);
        uint2 u3 = __ldg(&T2[(size_t)e3.x * 32 + lane]);
        float w0 = __int_as_float(e0.y), w1 = __int_as_float(e1.y);
        float w2 = __int_as_float(e2.y), w3 = __int_as_float(e3.y);
        float2 a0 = __half22float2(*(__half2*)&u0.x), b0 = __half22float2(*(__half2*)&u0.y);
        float2 a1 = __half22float2(*(__half2*)&u1.x), b1 = __half22float2(*(__half2*)&u1.y);
        float2 a2 = __half22float2(*(__half2*)&u2.x), b2 = __half22float2(*(__half2*)&u2.y);
        float2 a3 = __half22float2(*(__half2*)&u3.x), b3 = __half22float2(*(__half2*)&u3.y);
        ax += w0 * a0.x; ay += w0 * a0.y; az += w0 * b0.x; aw += w0 * b0.y;
        ax += w1 * a1.x; ay += w1 * a1.y; az += w1 * b1.x; aw += w1 * b1.y;
        ax += w2 * a2.x; ay += w2 * a2.y; az += w2 * b2.x; aw += w2 * b2.y;
        ax += w3 * a3.x; ay += w3 * a3.y; az += w3 * b3.x; aw += w3 * b3.y;
    }
    for (; p < e; p++) {
        int2 ed = __ldg(&g_edge[p]);
        float w = __int_as_float(ed.y);
        uint2 u = __ldg(&T2[(size_t)ed.x * 32 + lane]);
        float2 a = __half22float2(*(__half2*)&u.x);
        float2 b = __half22float2(*(__half2*)&u.y);
        ax += w * a.x; ay += w * a.y; az += w * b.x; aw += w * b.y;
    }

    ax = fmaxf(ax, 0.f); ay = fmaxf(ay, 0.f);
    az = fmaxf(az, 0.f); aw = fmaxf(aw, 0.f);

    if (SPLIT) {
        uint2 h, l;
        split2(ax, ay, h.x, l.x);
        split2(az, aw, h.y, l.y);
        ((uint2*)g_Ah)[(size_t)warp * 32 + lane] = h;
        ((uint2*)g_Al)[(size_t)warp * 32 + lane] = l;
    } else {
        ((float4*)O)[(size_t)warp * 32 + lane] = make_float4(ax, ay, az, aw);
    }
}

// ---------------- launch -----------------------------------------------------
extern "C" void kernel_launch(void* const* d_in, const int* in_sizes, int n_in,
                              void* d_out, int out_size)
{
    const float* x    = (const float*)d_in[0];
    const int*   erow = (const int*)  d_in[1];
    const int*   ecol = (const int*)  d_in[2];
    const float* ew   = (const float*)d_in[3];
    const float* w1   = (const float*)d_in[4];
    const float* w2   = (const float*)d_in[5];
    const float* w3   = (const float*)d_in[6];
    float* out = (float*)d_out;

    const int N = in_sizes[0] / FDIM;   // 100000
    const int E = in_sizes[1];          // 1600000

    __half* dT = nullptr;
    __nv_bfloat16 *dAh = nullptr, *dAl = nullptr, *dWh = nullptr, *dWl = nullptr;
    int* dCursor = nullptr;
    cudaGetSymbolAddress((void**)&dT, g_T);
    cudaGetSymbolAddress((void**)&dAh, g_Ah);
    cudaGetSymbolAddress((void**)&dAl, g_Al);
    cudaGetSymbolAddress((void**)&dWh, g_WhT);
    cudaGetSymbolAddress((void**)&dWl, g_WlT);
    cudaGetSymbolAddress((void**)&dCursor, g_cursor);

    cudaFuncSetAttribute(k_gemm_mma, cudaFuncAttributeMaxDynamicSharedMemorySize,
                         GEMM_SMEM_BYTES);

    // ---- pre-splits + CSR build ----
    k_split_w<<<dim3(64, 3), 256>>>(w1, w2, w3);
    k_split_x<<<(N * 32 + 255) / 256, 256>>>(x, N * 32);
    cudaMemsetAsync(dCursor, 0, (size_t)N * sizeof(int));
    k_hist<<<(E + 255) / 256, 256>>>(erow, E);
    int nb = (N + 1023) / 1024;
    k_scan1<<<nb, 1024>>>(N);
    k_scan2<<<1, 128>>>(nb);
    k_scan3<<<nb, 1024>>>(N, E);
    k_scatter<<<(E + 255) / 256, 256>>>(erow, ecol, ew, E);

    const int gemm_grid = (N + GBM - 1) / GBM;
    const int spmm_grid = (N + 7) / 8;

    // layer 1
    k_gemm_mma<<<gemm_grid, GT, GEMM_SMEM_BYTES>>>(dAh, dAl, dWh, dWl, dT, N);
    k_spmm_relu<1><<<spmm_grid, 256>>>(dT, nullptr, N);
    // layer 2
    k_gemm_mma<<<gemm_grid, GT, GEMM_SMEM_BYTES>>>(dAh, dAl, dWh + 16384, dWl + 16384, dT, N);
    k_spmm_relu<1><<<spmm_grid, 256>>>(dT, nullptr, N);
    // layer 3
    k_gemm_mma<<<gemm_grid, GT, GEMM_SMEM_BYTES>>>(dAh, dAl, dWh + 32768, dWl + 32768, dT, N);
    k_spmm_relu<0><<<spmm_grid, 256>>>(dT, out, N);
}

// round 17
// speedup vs baseline: 1.8461x; 1.0321x over previous
#include <cuda_runtime.h>
#include <cuda_bf16.h>
#include <cuda_fp16.h>
#include <cstdint>

// Problem constants (fixed by the reference)
#define NMAX 100000
#define EMAX 1600000
#define FDIM 128

// ---------------- scratch (static device globals; no runtime allocation) ----
__device__ __half          g_T[(size_t)NMAX * FDIM];   // GEMM output (fp16, gathered)
__device__ __nv_bfloat16   g_Ah[(size_t)NMAX * FDIM];  // GEMM input, hi part
__device__ __nv_bfloat16   g_Al[(size_t)NMAX * FDIM];  // GEMM input, lo part
__device__ __nv_bfloat16   g_WhT[3 * 128 * 128];       // W^T hi, [layer][n][k]
__device__ __nv_bfloat16   g_WlT[3 * 128 * 128];       // W^T lo
__device__ int   g_rowptr[NMAX + 1];
__device__ int   g_cursor[NMAX];
__device__ int2  g_edge[EMAX];                         // {col, weight-bits}
__device__ int   g_bsum[256];

// ---------------- hi/lo split helpers ---------------------------------------
__device__ __forceinline__ void split2(float a, float b, uint32_t& hi, uint32_t& lo) {
    __nv_bfloat16 ha = __float2bfloat16(a);
    __nv_bfloat16 hb = __float2bfloat16(b);
    __nv_bfloat162 h; h.x = ha; h.y = hb;
    __nv_bfloat162 l;
    l.x = __float2bfloat16(a - __bfloat162float(ha));
    l.y = __float2bfloat16(b - __bfloat162float(hb));
    hi = *(uint32_t*)&h;
    lo = *(uint32_t*)&l;
}

// ---------------- weight pre-split (once; 3 layers) --------------------------
__global__ void k_split_w(const float* __restrict__ w1, const float* __restrict__ w2,
                          const float* __restrict__ w3) {
    const float* W = (blockIdx.y == 0) ? w1 : (blockIdx.y == 1) ? w2 : w3;
    __nv_bfloat16* Wh = g_WhT + blockIdx.y * 16384;
    __nv_bfloat16* Wl = g_WlT + blockIdx.y * 16384;
    int i = blockIdx.x * 256 + threadIdx.x;   // i = n*128 + k
    int n = i >> 7, k = i & 127;
    float v = W[k * 128 + n];
    __nv_bfloat16 hi = __float2bfloat16(v);
    Wh[i] = hi;
    Wl[i] = __float2bfloat16(v - __bfloat162float(hi));
}

// ---------------- layer-1 input split ----------------------------------------
__global__ void k_split_x(const float* __restrict__ X, int n4) {
    int i = blockIdx.x * 256 + threadIdx.x;
    if (i >= n4) return;
    float4 v = ((const float4*)X)[i];
    uint2 h, l;
    split2(v.x, v.y, h.x, l.x);
    split2(v.z, v.w, h.y, l.y);
    ((uint2*)g_Ah)[i] = h;
    ((uint2*)g_Al)[i] = l;
}

// ---------------- CSR build --------------------------------------------------
__global__ void k_hist(const int* __restrict__ erow, int E) {
    int e = blockIdx.x * blockDim.x + threadIdx.x;
    if (e < E) atomicAdd(&g_cursor[erow[e]], 1);
}

__global__ void k_scan1(int n) {
    __shared__ int s[1024];
    int i = blockIdx.x * 1024 + threadIdx.x;
    int v = (i < n) ? g_cursor[i] : 0;
    s[threadIdx.x] = v;
    __syncthreads();
#pragma unroll
    for (int off = 1; off < 1024; off <<= 1) {
        int t = 0;
        if ((int)threadIdx.x >= off) t = s[threadIdx.x - off];
        __syncthreads();
        s[threadIdx.x] += t;
        __syncthreads();
    }
    if (i < n) g_rowptr[i] = s[threadIdx.x] - v;
    if (threadIdx.x == 1023) g_bsum[blockIdx.x] = s[1023];
}

__global__ void k_scan2(int nb) {
    __shared__ int s[128];
    int t = threadIdx.x;
    int v = (t < nb) ? g_bsum[t] : 0;
    s[t] = v;
    __syncthreads();
#pragma unroll
    for (int off = 1; off < 128; off <<= 1) {
        int u = (t >= off) ? s[t - off] : 0;
        __syncthreads();
        s[t] += u;
        __syncthreads();
    }
    if (t < nb) g_bsum[t] = s[t] - v;   // exclusive
}

__global__ void k_scan3(int n, int E) {
    int i = blockIdx.x * 1024 + threadIdx.x;
    if (i < n) {
        int rp = g_rowptr[i] + g_bsum[blockIdx.x];
        g_rowptr[i] = rp;
        g_cursor[i] = rp;
    }
    if (blockIdx.x == 0 && threadIdx.x == 0) g_rowptr[n] = E;
}

__global__ void k_scatter(const int* __restrict__ erow, const int* __restrict__ ecol,
                          const float* __restrict__ ew, int E) {
    int e = blockIdx.x * blockDim.x + threadIdx.x;
    if (e < E) {
        int p = atomicAdd(&g_cursor[erow[e]], 1);
        g_edge[p] = make_int2(ecol[e], __float_as_int(ew[e]));
    }
}

// ---------------- GEMM: T[N,128] = A[N,128] @ W[128,128] ---------------------
// bf16-split 3-term tensor-core GEMM. ldmatrix fragment loads; GBM=64 /
// 128-thread CTAs -> 104 KB smem -> 2 CTAs per SM (load/compute overlap).
#define GT 128
#define GBM 64
#define LDA 136
#define SM_A (GBM * LDA)
#define SM_B (128 * LDA)
#define GEMM_SMEM_BYTES ((2 * SM_A + 2 * SM_B) * 2)   // 104448 B

__device__ __forceinline__ void mma16816(float* c, const uint32_t* a,
                                         uint32_t b0, uint32_t b1) {
    asm volatile(
        "mma.sync.aligned.m16n8k16.row.col.f32.bf16.bf16.f32 "
        "{%0,%1,%2,%3}, {%4,%5,%6,%7}, {%8,%9}, {%0,%1,%2,%3};\n"
        : "+f"(c[0]), "+f"(c[1]), "+f"(c[2]), "+f"(c[3])
        : "r"(a[0]), "r"(a[1]), "r"(a[2]), "r"(a[3]), "r"(b0), "r"(b1));
}

__device__ __forceinline__ void ldsm4(uint32_t* r, uint32_t addr) {
    asm volatile(
        "ldmatrix.sync.aligned.m8n8.x4.shared.b16 {%0,%1,%2,%3}, [%4];\n"
        : "=r"(r[0]), "=r"(r[1]), "=r"(r[2]), "=r"(r[3]) : "r"(addr));
}

__global__ __launch_bounds__(GT) void k_gemm_mma(
    const __nv_bfloat16* __restrict__ Agh, const __nv_bfloat16* __restrict__ Agl,
    const __nv_bfloat16* __restrict__ Wh,  const __nv_bfloat16* __restrict__ Wl,
    __half* __restrict__ C, int N)
{
    extern __shared__ __nv_bfloat16 sm[];
    __nv_bfloat16* Ah = sm;                  // [64][LDA]
    __nv_bfloat16* Al = Ah + SM_A;
    __nv_bfloat16* Bh = Al + SM_A;           // [128][LDA] ([n][k])
    __nv_bfloat16* Bl = Bh + SM_B;

    const int tid = threadIdx.x;
    const int m_base = blockIdx.x * GBM;

    // ---- tile loads: uint4 (8 bf16), fully coalesced ----
    {
        const uint4* A4h = (const uint4*)Agh;
        const uint4* A4l = (const uint4*)Agl;
        const uint4 z = make_uint4(0, 0, 0, 0);
#pragma unroll
        for (int it = 0; it < 8; it++) {                 // A: 1024 uint4 per array
            int i = tid + it * GT;
            int r = i >> 4, kq = i & 15;
            bool ok = (m_base + r) < N;
            uint4 va = ok ? A4h[(size_t)(m_base + r) * 16 + kq] : z;
            uint4 vb = ok ? A4l[(size_t)(m_base + r) * 16 + kq] : z;
            *(uint4*)(Ah + r * LDA + kq * 8) = va;
            *(uint4*)(Al + r * LDA + kq * 8) = vb;
        }
        const uint4* B4h = (const uint4*)Wh;
        const uint4* B4l = (const uint4*)Wl;
#pragma unroll
        for (int it = 0; it < 16; it++) {                // B: 2048 uint4 per array
            int i = tid + it * GT;
            int r = i >> 4, kq = i & 15;
            *(uint4*)(Bh + r * LDA + kq * 8) = B4h[i];
            *(uint4*)(Bl + r * LDA + kq * 8) = B4l[i];
        }
    }
    __syncthreads();

    const int warp = tid >> 5, lane = tid & 31;
    const int m0 = warp * 16;

    // ldmatrix per-lane addresses
    // A (m16k16, x4): matrices {rows m0..+7,k0-7}{m0+8..15,k0-7}{..,k8-15}{..}
    const uint32_t aOff =
        (uint32_t)(((m0 + (lane & 15)) * LDA + ((lane >> 4) << 3)) * 2);
    const uint32_t aBaseH = (uint32_t)__cvta_generic_to_shared(Ah) + aOff;
    const uint32_t aBaseL = (uint32_t)__cvta_generic_to_shared(Al) + aOff;
    // B (two n8k16 frags per x4): groups of 8 lanes -> (n blk, k blk):
    //   g0:(n+0..7,k0) g1:(n+0..7,k8) g2:(n+8..15,k0) g3:(n+8..15,k8)
    const uint32_t bOff =
        (uint32_t)(((((lane & 7) + ((lane >> 4) << 3)) * LDA) +
                    (((lane >> 3) & 1) << 3)) * 2);
    const uint32_t bBaseH = (uint32_t)__cvta_generic_to_shared(Bh) + bOff;
    const uint32_t bBaseL = (uint32_t)__cvta_generic_to_shared(Bl) + bOff;

    float acc[64];
#pragma unroll
    for (int i = 0; i < 64; i++) acc[i] = 0.f;

#pragma unroll
    for (int ks = 0; ks < 8; ks++) {
        const uint32_t kb = ks * 32;      // 16 bf16 = 32 bytes along k
        uint32_t ah[4], al[4];
        ldsm4(ah, aBaseH + kb);
        ldsm4(al, aBaseL + kb);
#pragma unroll
        for (int j = 0; j < 8; j++) {     // pair of n8 tiles per iteration
            const uint32_t boff = (uint32_t)(j * (16 * LDA * 2)) + kb;
            uint32_t bh[4], bl[4];
            ldsm4(bh, bBaseH + boff);
            ldsm4(bl, bBaseL + boff);
            float* c0 = acc + (2 * j) * 4;
            float* c1 = acc + (2 * j + 1) * 4;
            mma16816(c0, ah, bh[0], bh[1]);
            mma16816(c0, ah, bl[0], bl[1]);
            mma16816(c0, al, bh[0], bh[1]);
            mma16816(c1, ah, bh[2], bh[3]);
            mma16816(c1, ah, bl[2], bl[3]);
            mma16816(c1, al, bh[2], bh[3]);
        }
    }

    // epilogue: fp16 store
    const int qr = lane >> 2;
    const int qk = (lane & 3) * 2;
#pragma unroll
    for (int nt = 0; nt < 16; nt++) {
        const int col = nt * 8 + qk;
        const int r0 = m_base + m0 + qr;
        const int r1 = r0 + 8;
        __half2 h0 = __floats2half2_rn(acc[nt * 4 + 0], acc[nt * 4 + 1]);
        __half2 h1 = __floats2half2_rn(acc[nt * 4 + 2], acc[nt * 4 + 3]);
        if (r0 < N) *(__half2*)(C + (size_t)r0 * 128 + col) = h0;
        if (r1 < N) *(__half2*)(C + (size_t)r1 * 128 + col) = h1;
    }
}

// ---------------- SpMM (CSR) + ReLU ------------------------------------------
template <int SPLIT>
__global__ __launch_bounds__(256) void k_spmm_relu(
    const __half* __restrict__ T, float* __restrict__ O, int N)
{
    int warp = (blockIdx.x * blockDim.x + threadIdx.x) >> 5;
    int lane = threadIdx.x & 31;
    if (warp >= N) return;

    int s = g_rowptr[warp];
    int e = g_rowptr[warp + 1];

    float ax = 0.f, ay = 0.f, az = 0.f, aw = 0.f;
    const uint2* T2 = (const uint2*)T;   // index = row*32 + lane

    int p = s;
#pragma unroll 1
    for (; p + 4 <= e; p += 4) {
        int2 e0 = __ldg(&g_edge[p]),     e1 = __ldg(&g_edge[p + 1]);
        int2 e2 = __ldg(&g_edge[p + 2]), e3 = __ldg(&g_edge[p + 3]);
        uint2 u0 = __ldg(&T2[(size_t)e0.x * 32 + lane]);
        uint2 u1 = __ldg(&T2[(size_t)e1.x * 32 + lane]);
        uint2 u2 = __ldg(&T2[(size_t)e2.x * 32 + lane]);
        uint2 u3 = __ldg(&T2[(size_t)e3.x * 32 + lane]);
        float w0 = __int_as_float(e0.y), w1 = __int_as_float(e1.y);
        float w2 = __int_as_float(e2.y), w3 = __int_as_float(e3.y);
        float2 a0 = __half22float2(*(__half2*)&u0.x), b0 = __half22float2(*(__half2*)&u0.y);
        float2 a1 = __half22float2(*(__half2*)&u1.x), b1 = __half22float2(*(__half2*)&u1.y);
        float2 a2 = __half22float2(*(__half2*)&u2.x), b2 = __half22float2(*(__half2*)&u2.y);
        float2 a3 = __half22float2(*(__half2*)&u3.x), b3 = __half22float2(*(__half2*)&u3.y);
        ax += w0 * a0.x; ay += w0 * a0.y; az += w0 * b0.x; aw += w0 * b0.y;
        ax += w1 * a1.x; ay += w1 * a1.y; az += w1 * b1.x; aw += w1 * b1.y;
        ax += w2 * a2.x; ay += w2 * a2.y; az += w2 * b2.x; aw += w2 * b2.y;
        ax += w3 * a3.x; ay += w3 * a3.y; az += w3 * b3.x; aw += w3 * b3.y;
    }
    for (; p < e; p++) {
        int2 ed = __ldg(&g_edge[p]);
        float w = __int_as_float(ed.y);
        uint2 u = __ldg(&T2[(size_t)ed.x * 32 + lane]);
        float2 a = __half22float2(*(__half2*)&u.x);
        float2 b = __half22float2(*(__half2*)&u.y);
        ax += w * a.x; ay += w * a.y; az += w * b.x; aw += w * b.y;
    }

    ax = fmaxf(ax, 0.f); ay = fmaxf(ay, 0.f);
    az = fmaxf(az, 0.f); aw = fmaxf(aw, 0.f);

    if (SPLIT) {
        uint2 h, l;
        split2(ax, ay, h.x, l.x);
        split2(az, aw, h.y, l.y);
        ((uint2*)g_Ah)[(size_t)warp * 32 + lane] = h;
        ((uint2*)g_Al)[(size_t)warp * 32 + lane] = l;
    } else {
        ((float4*)O)[(size_t)warp * 32 + lane] = make_float4(ax, ay, az, aw);
    }
}

// ---------------- launch -----------------------------------------------------
extern "C" void kernel_launch(void* const* d_in, const int* in_sizes, int n_in,
                              void* d_out, int out_size)
{
    const float* x    = (const float*)d_in[0];
    const int*   erow = (const int*)  d_in[1];
    const int*   ecol = (const int*)  d_in[2];
    const float* ew   = (const float*)d_in[3];
    const float* w1   = (const float*)d_in[4];
    const float* w2   = (const float*)d_in[5];
    const float* w3   = (const float*)d_in[6];
    float* out = (float*)d_out;

    const int N = in_sizes[0] / FDIM;   // 100000
    const int E = in_sizes[1];          // 1600000

    __half* dT = nullptr;
    __nv_bfloat16 *dAh = nullptr, *dAl = nullptr, *dWh = nullptr, *dWl = nullptr;
    int* dCursor = nullptr;
    cudaGetSymbolAddress((void**)&dT, g_T);
    cudaGetSymbolAddress((void**)&dAh, g_Ah);
    cudaGetSymbolAddress((void**)&dAl, g_Al);
    cudaGetSymbolAddress((void**)&dWh, g_WhT);
    cudaGetSymbolAddress((void**)&dWl, g_WlT);
    cudaGetSymbolAddress((void**)&dCursor, g_cursor);

    cudaFuncSetAttribute(k_gemm_mma, cudaFuncAttributeMaxDynamicSharedMemorySize,
                         GEMM_SMEM_BYTES);

    // ---- fork: CSR build on side stream, overlapped with splits + GEMM1 ----
    // (stream/events created per call; never destroyed while capture is live —
    //  kernel_launch runs only a handful of times, leak is bounded and host-side)
    cudaStream_t s1;
    cudaStreamCreate(&s1);
    cudaEvent_t evFork, evJoin;
    cudaEventCreateWithFlags(&evFork, cudaEventDisableTiming);
    cudaEventCreateWithFlags(&evJoin, cudaEventDisableTiming);

    cudaEventRecord(evFork, 0);
    cudaStreamWaitEvent(s1, evFork, 0);

    cudaMemsetAsync(dCursor, 0, (size_t)N * sizeof(int), s1);
    k_hist<<<(E + 255) / 256, 256, 0, s1>>>(erow, E);
    int nb = (N + 1023) / 1024;
    k_scan1<<<nb, 1024, 0, s1>>>(N);
    k_scan2<<<1, 128, 0, s1>>>(nb);
    k_scan3<<<nb, 1024, 0, s1>>>(N, E);
    k_scatter<<<(E + 255) / 256, 256, 0, s1>>>(erow, ecol, ew, E);
    cudaEventRecord(evJoin, s1);

    // main stream: pre-splits + layer-1 GEMM (independent of CSR)
    k_split_w<<<dim3(64, 3), 256>>>(w1, w2, w3);
    k_split_x<<<(N * 32 + 255) / 256, 256>>>(x, N * 32);

    const int gemm_grid = (N + GBM - 1) / GBM;
    const int spmm_grid = (N + 7) / 8;

    k_gemm_mma<<<gemm_grid, GT, GEMM_SMEM_BYTES>>>(dAh, dAl, dWh, dWl, dT, N);

    cudaStreamWaitEvent(0, evJoin, 0);   // join CSR before first SpMM

    k_spmm_relu<1><<<spmm_grid, 256>>>(dT, nullptr, N);
    // layer 2
    k_gemm_mma<<<gemm_grid, GT, GEMM_SMEM_BYTES>>>(dAh, dAl, dWh + 16384, dWl + 16384, dT, N);
    k_spmm_relu<1><<<spmm_grid, 256>>>(dT, nullptr, N);
    // layer 3
    k_gemm_mma<<<gemm_grid, GT, GEMM_SMEM_BYTES>>>(dAh, dAl, dWh + 32768, dWl + 32768, dT, N);
    k_spmm_relu<0><<<spmm_grid, 256>>>(dT, out, N);
}